// round 1
// baseline (speedup 1.0000x reference)
#include <cuda_runtime.h>
#include <math.h>

#define BATCH 4
#define SEQ   2048
#define DMODEL 1024
#define NHEAD 16
#define DHEAD 64
#define MROWS (BATCH * SEQ)   // 8192

// Scratch (device globals: allocation-free, graph-capture safe)
__device__ float g_q[MROWS * DMODEL];
__device__ float g_k[MROWS * DMODEL];
__device__ float g_v[MROWS * DMODEL];
__device__ float g_ctx[MROWS * DMODEL];

// ---------------------------------------------------------------------------
// C[m,n] = sum_k A[m,k] * W[n,k]   (A: [M,K] row-major, W: [N,K] row-major)
// 128x128x16 block tile, 8x8 per-thread tile, 256 threads.
// ---------------------------------------------------------------------------
__global__ __launch_bounds__(256) void gemm_nt_kernel(
    const float* __restrict__ A, const float* __restrict__ W,
    float* __restrict__ C, int M, int N, int K)
{
    constexpr int BM = 128, BN = 128, BK = 16, TM = 8, TN = 8;
    __shared__ float As[BK][BM + 4];
    __shared__ float Bs[BK][BN + 4];

    const int tid = threadIdx.x;
    const int tx = tid & 15;
    const int ty = tid >> 4;
    const int m0 = blockIdx.y * BM;
    const int n0 = blockIdx.x * BN;

    float acc[TM][TN];
#pragma unroll
    for (int i = 0; i < TM; i++)
#pragma unroll
        for (int j = 0; j < TN; j++) acc[i][j] = 0.0f;

    for (int k0 = 0; k0 < K; k0 += BK) {
        // Load tiles: 128 rows x 16 k, float4 along k. 512 float4 / 256 thr = 2 each.
#pragma unroll
        for (int t = 0; t < 2; t++) {
            int id  = tid + t * 256;
            int row = id >> 2;
            int kq  = (id & 3) * 4;
            float4 va = *(const float4*)(A + (m0 + row) * K + k0 + kq);
            As[kq + 0][row] = va.x;
            As[kq + 1][row] = va.y;
            As[kq + 2][row] = va.z;
            As[kq + 3][row] = va.w;
            float4 vb = *(const float4*)(W + (n0 + row) * K + k0 + kq);
            Bs[kq + 0][row] = vb.x;
            Bs[kq + 1][row] = vb.y;
            Bs[kq + 2][row] = vb.z;
            Bs[kq + 3][row] = vb.w;
        }
        __syncthreads();

#pragma unroll
        for (int kk = 0; kk < BK; kk++) {
            float a[TM], b[TN];
            float4 a0 = *(const float4*)&As[kk][ty * TM + 0];
            float4 a1 = *(const float4*)&As[kk][ty * TM + 4];
            a[0] = a0.x; a[1] = a0.y; a[2] = a0.z; a[3] = a0.w;
            a[4] = a1.x; a[5] = a1.y; a[6] = a1.z; a[7] = a1.w;
            float4 b0 = *(const float4*)&Bs[kk][tx * TN + 0];
            float4 b1 = *(const float4*)&Bs[kk][tx * TN + 4];
            b[0] = b0.x; b[1] = b0.y; b[2] = b0.z; b[3] = b0.w;
            b[4] = b1.x; b[5] = b1.y; b[6] = b1.z; b[7] = b1.w;
#pragma unroll
            for (int i = 0; i < TM; i++)
#pragma unroll
                for (int j = 0; j < TN; j++)
                    acc[i][j] += a[i] * b[j];
        }
        __syncthreads();
    }

#pragma unroll
    for (int i = 0; i < TM; i++) {
#pragma unroll
        for (int j = 0; j < TN; j += 4) {
            float4 o = make_float4(acc[i][j], acc[i][j + 1], acc[i][j + 2], acc[i][j + 3]);
            *(float4*)(C + (m0 + ty * TM + i) * N + n0 + tx * TN + j) = o;
        }
    }
}

// ---------------------------------------------------------------------------
// Fused flash attention (fp32, online softmax).
// grid = (S/64, H, B), block = 256 threads (16x16).
// Q tile: 64 rows. KV tiles: 32 rows streamed over S.
// Per-thread: S fragment 4x2, O fragment 4x4 (rows ty*4+i, cols tx-mapped).
// ---------------------------------------------------------------------------
__global__ __launch_bounds__(256) void flash_attn_kernel(
    const float* __restrict__ Q, const float* __restrict__ K,
    const float* __restrict__ V, float* __restrict__ O)
{
    constexpr int BM = 64, BN = 32;
    constexpr float SCALE = 0.125f;  // 1/sqrt(64)

    __shared__ float Qs[BM][DHEAD + 4];   // 64 x 68
    __shared__ float KVbuf[2176];         // union: Kt[d*33+kn] (64x33) | Vs[k*68+d] (32x68)
    __shared__ float Ss[BM][BN + 1];      // 64 x 33
    __shared__ float mrow[BM], lrow[BM], arow[BM];

    float* Kt = KVbuf;
    float* Vs = KVbuf;

    const int tid = threadIdx.x;
    const int tx = tid & 15;
    const int ty = tid >> 4;
    const int q0 = blockIdx.x * BM;
    const int h  = blockIdx.y;
    const int b  = blockIdx.z;

    const float* Qb = Q + (b * SEQ + q0) * DMODEL + h * DHEAD;
    const float* Kb = K + (b * SEQ) * DMODEL + h * DHEAD;
    const float* Vb = V + (b * SEQ) * DMODEL + h * DHEAD;

    // Load Q tile (64 x 64 floats = 1024 float4)
#pragma unroll
    for (int t = 0; t < 4; t++) {
        int id  = tid + t * 256;
        int row = id >> 4;
        int d4  = (id & 15) * 4;
        float4 v = *(const float4*)(Qb + row * DMODEL + d4);
        *(float4*)&Qs[row][d4] = v;
    }
    if (tid < BM) { mrow[tid] = -INFINITY; lrow[tid] = 0.0f; }

    float o[4][4];
#pragma unroll
    for (int i = 0; i < 4; i++)
#pragma unroll
        for (int j = 0; j < 4; j++) o[i][j] = 0.0f;

    const int qr = ty * 4;   // this thread's first q row
    const int kc = tx * 2;   // this thread's first score col
    const int dc = tx * 4;   // this thread's first output col

    for (int kv0 = 0; kv0 < SEQ; kv0 += BN) {
        __syncthreads();  // previous iter's Vs reads done before overwriting

        // Load K tile transposed: Kt[d][kn]
#pragma unroll
        for (int t = 0; t < 2; t++) {
            int id = tid + t * 256;
            int kn = id >> 4;
            int d4 = (id & 15) * 4;
            float4 v = *(const float4*)(Kb + (kv0 + kn) * DMODEL + d4);
            Kt[(d4 + 0) * 33 + kn] = v.x;
            Kt[(d4 + 1) * 33 + kn] = v.y;
            Kt[(d4 + 2) * 33 + kn] = v.z;
            Kt[(d4 + 3) * 33 + kn] = v.w;
        }
        __syncthreads();

        // S = Q K^T * scale  (fragment: 4 rows x 2 cols)
        float s[4][2];
#pragma unroll
        for (int i = 0; i < 4; i++) { s[i][0] = 0.0f; s[i][1] = 0.0f; }

#pragma unroll
        for (int d = 0; d < DHEAD; d += 4) {
            float a0[4], a1[4], a2[4], a3[4];
            *(float4*)a0 = *(const float4*)&Qs[qr + 0][d];
            *(float4*)a1 = *(const float4*)&Qs[qr + 1][d];
            *(float4*)a2 = *(const float4*)&Qs[qr + 2][d];
            *(float4*)a3 = *(const float4*)&Qs[qr + 3][d];
#pragma unroll
            for (int e = 0; e < 4; e++) {
                float b0 = Kt[(d + e) * 33 + kc + 0];
                float b1 = Kt[(d + e) * 33 + kc + 1];
                s[0][0] += a0[e] * b0;  s[0][1] += a0[e] * b1;
                s[1][0] += a1[e] * b0;  s[1][1] += a1[e] * b1;
                s[2][0] += a2[e] * b0;  s[2][1] += a2[e] * b1;
                s[3][0] += a3[e] * b0;  s[3][1] += a3[e] * b1;
            }
        }
#pragma unroll
        for (int i = 0; i < 4; i++) {
            Ss[qr + i][kc + 0] = s[i][0] * SCALE;
            Ss[qr + i][kc + 1] = s[i][1] * SCALE;
        }
        __syncthreads();

        // Online softmax: one thread per q row (warps 0-1)
        if (tid < BM) {
            int r = tid;
            float mold = mrow[r];
            float mx = mold;
#pragma unroll
            for (int j = 0; j < BN; j++) mx = fmaxf(mx, Ss[r][j]);
            float al = __expf(mold - mx);
            float sum = 0.0f;
#pragma unroll
            for (int j = 0; j < BN; j++) {
                float p = __expf(Ss[r][j] - mx);
                Ss[r][j] = p;
                sum += p;
            }
            lrow[r] = lrow[r] * al + sum;
            mrow[r] = mx;
            arow[r] = al;
        }

        // Load V tile (reuses Kt storage — all Kt reads completed above)
#pragma unroll
        for (int t = 0; t < 2; t++) {
            int id = tid + t * 256;
            int kn = id >> 4;
            int d4 = (id & 15) * 4;
            float4 v = *(const float4*)(Vb + (kv0 + kn) * DMODEL + d4);
            *(float4*)&Vs[kn * 68 + d4] = v;
        }
        __syncthreads();

        // O = O*alpha + P V
        float al0 = arow[qr + 0], al1 = arow[qr + 1];
        float al2 = arow[qr + 2], al3 = arow[qr + 3];
#pragma unroll
        for (int j = 0; j < 4; j++) {
            o[0][j] *= al0; o[1][j] *= al1; o[2][j] *= al2; o[3][j] *= al3;
        }
#pragma unroll
        for (int k = 0; k < BN; k++) {
            float p0 = Ss[qr + 0][k];
            float p1 = Ss[qr + 1][k];
            float p2 = Ss[qr + 2][k];
            float p3 = Ss[qr + 3][k];
            float vv[4];
            *(float4*)vv = *(const float4*)&Vs[k * 68 + dc];
#pragma unroll
            for (int j = 0; j < 4; j++) {
                o[0][j] += p0 * vv[j];
                o[1][j] += p1 * vv[j];
                o[2][j] += p2 * vv[j];
                o[3][j] += p3 * vv[j];
            }
        }
    }

    // Epilogue: normalize and write ctx[b, q, h*64 + d]
    float* Ob = O + (b * SEQ + q0) * DMODEL + h * DHEAD;
#pragma unroll
    for (int i = 0; i < 4; i++) {
        float linv = 1.0f / lrow[qr + i];
        float4 r = make_float4(o[i][0] * linv, o[i][1] * linv,
                               o[i][2] * linv, o[i][3] * linv);
        *(float4*)(Ob + (qr + i) * DMODEL + dc) = r;
    }
}

// ---------------------------------------------------------------------------

extern "C" void kernel_launch(void* const* d_in, const int* in_sizes, int n_in,
                              void* d_out, int out_size)
{
    const float* X  = (const float*)d_in[0];
    const float* Wq = (const float*)d_in[1];
    const float* Wk = (const float*)d_in[2];
    const float* Wv = (const float*)d_in[3];
    const float* Wo = (const float*)d_in[4];
    float* out = (float*)d_out;

    float *q, *k, *v, *ctx;
    cudaGetSymbolAddress((void**)&q,   g_q);
    cudaGetSymbolAddress((void**)&k,   g_k);
    cudaGetSymbolAddress((void**)&v,   g_v);
    cudaGetSymbolAddress((void**)&ctx, g_ctx);

    dim3 gproj(DMODEL / 128, MROWS / 128);   // (8, 64)
    gemm_nt_kernel<<<gproj, 256>>>(X, Wq, q, MROWS, DMODEL, DMODEL);
    gemm_nt_kernel<<<gproj, 256>>>(X, Wk, k, MROWS, DMODEL, DMODEL);
    gemm_nt_kernel<<<gproj, 256>>>(X, Wv, v, MROWS, DMODEL, DMODEL);

    dim3 gattn(SEQ / 64, NHEAD, BATCH);      // (32, 16, 4)
    flash_attn_kernel<<<gattn, 256>>>(q, k, v, ctx);

    gemm_nt_kernel<<<gproj, 256>>>(ctx, Wo, out, MROWS, DMODEL, DMODEL);
}

// round 2
// speedup vs baseline: 2.5242x; 2.5242x over previous
#include <cuda_runtime.h>
#include <math.h>
#include <stdint.h>

#define BATCH 4
#define SEQ   2048
#define DMODEL 1024
#define NHEAD 16
#define DHEAD 64
#define MROWS (BATCH * SEQ)   // 8192

// Scratch (device globals: allocation-free, graph-capture safe)
__device__ float g_q[MROWS * DMODEL];
__device__ float g_k[MROWS * DMODEL];
__device__ float g_v[MROWS * DMODEL];
__device__ float g_ctx[MROWS * DMODEL];

// ---------------------------------------------------------------------------
// helpers
// ---------------------------------------------------------------------------
__device__ __forceinline__ uint32_t f2tf32(float x) {
    uint32_t r;
    asm("cvt.rna.tf32.f32 %0, %1;" : "=r"(r) : "f"(x));
    return r;
}
__device__ __forceinline__ float4 cvt4(float4 v) {
    v.x = __uint_as_float(f2tf32(v.x));
    v.y = __uint_as_float(f2tf32(v.y));
    v.z = __uint_as_float(f2tf32(v.z));
    v.w = __uint_as_float(f2tf32(v.w));
    return v;
}
// D += A(16x8) * B(8x8), tf32 inputs (as b32 regs), f32 accum
__device__ __forceinline__ void mma_tf32(float d[4], const uint32_t a[4], const uint32_t b[2]) {
    asm volatile(
        "mma.sync.aligned.m16n8k8.row.col.f32.tf32.tf32.f32 "
        "{%0,%1,%2,%3},{%4,%5,%6,%7},{%8,%9},{%0,%1,%2,%3};"
        : "+f"(d[0]), "+f"(d[1]), "+f"(d[2]), "+f"(d[3])
        : "r"(a[0]), "r"(a[1]), "r"(a[2]), "r"(a[3]), "r"(b[0]), "r"(b[1]));
}

// ---------------------------------------------------------------------------
// C[m,n] = sum_k A[m,k] * W[n,k]  via tf32 tensor cores.
// Block 128x128x32, 256 threads = 8 warps (2m x 4n), warp tile 64x32.
// ---------------------------------------------------------------------------
__global__ __launch_bounds__(256) void gemm_nt_tc(
    const float* __restrict__ A, const float* __restrict__ W,
    float* __restrict__ C, int M, int N, int K)
{
    constexpr int BM = 128, BN = 128, BK = 32, PAD = 36;  // 36%32=4 -> banks 4g+t
    __shared__ float As[BM * PAD];
    __shared__ float Bs[BN * PAD];

    const int tid = threadIdx.x;
    const int lane = tid & 31, warp = tid >> 5;
    const int g = lane >> 2, tg = lane & 3;
    const int m0 = blockIdx.y * BM, n0 = blockIdx.x * BN;
    const int wm = (warp >> 2) * 64;   // 0 or 64
    const int wn = (warp & 3) * 32;    // 0,32,64,96

    float acc[4][4][4];
#pragma unroll
    for (int mt = 0; mt < 4; mt++)
#pragma unroll
        for (int nt = 0; nt < 4; nt++)
#pragma unroll
            for (int e = 0; e < 4; e++) acc[mt][nt][e] = 0.0f;

    for (int k0 = 0; k0 < K; k0 += BK) {
        // load & convert tiles: 128 rows x 32 k each, 1024 float4 per matrix
#pragma unroll
        for (int t = 0; t < 4; t++) {
            int id = t * 256 + tid;
            int row = id >> 3;
            int kq = (id & 7) * 4;
            float4 va = *(const float4*)(A + (size_t)(m0 + row) * K + k0 + kq);
            float4 vb = *(const float4*)(W + (size_t)(n0 + row) * K + k0 + kq);
            *(float4*)&As[row * PAD + kq] = cvt4(va);
            *(float4*)&Bs[row * PAD + kq] = cvt4(vb);
        }
        __syncthreads();

#pragma unroll
        for (int ks = 0; ks < BK; ks += 8) {
            uint32_t af[4][4], bf[4][2];
#pragma unroll
            for (int mt = 0; mt < 4; mt++) {
                const float* p = &As[(wm + mt * 16 + g) * PAD + ks + tg];
                af[mt][0] = __float_as_uint(p[0]);
                af[mt][1] = __float_as_uint(p[8 * PAD]);
                af[mt][2] = __float_as_uint(p[4]);
                af[mt][3] = __float_as_uint(p[8 * PAD + 4]);
            }
#pragma unroll
            for (int nt = 0; nt < 4; nt++) {
                const float* p = &Bs[(wn + nt * 8 + g) * PAD + ks + tg];
                bf[nt][0] = __float_as_uint(p[0]);
                bf[nt][1] = __float_as_uint(p[4]);
            }
#pragma unroll
            for (int mt = 0; mt < 4; mt++)
#pragma unroll
                for (int nt = 0; nt < 4; nt++)
                    mma_tf32(acc[mt][nt], af[mt], bf[nt]);
        }
        __syncthreads();
    }

#pragma unroll
    for (int mt = 0; mt < 4; mt++) {
        int r0 = m0 + wm + mt * 16 + g;
#pragma unroll
        for (int nt = 0; nt < 4; nt++) {
            int c = n0 + wn + nt * 8 + 2 * tg;
            *(float2*)(C + (size_t)r0 * N + c)       = make_float2(acc[mt][nt][0], acc[mt][nt][1]);
            *(float2*)(C + (size_t)(r0 + 8) * N + c) = make_float2(acc[mt][nt][2], acc[mt][nt][3]);
        }
    }
}

// ---------------------------------------------------------------------------
// Flash attention with tf32 mma. grid=(S/64, H, B), 256 threads = 8 warps.
// Warp tile 32x16 (2 mtiles x 2 ntiles of m16n8) for both S (64x64) and O (64x64).
// ---------------------------------------------------------------------------
__global__ __launch_bounds__(256) void flash_attn_tc(
    const float* __restrict__ Q, const float* __restrict__ K,
    const float* __restrict__ V, float* __restrict__ O)
{
    constexpr int BM = 64, BN = 64, PAD = 68;  // 68%32=4 -> banks 4g+t
    constexpr float SCALE = 0.125f;            // 1/sqrt(64)

    extern __shared__ float sm[];
    float* Qs   = sm;                  // 64*68
    float* Ks   = Qs + BM * PAD;       // 64*68
    float* Vs   = Ks + BN * PAD;       // 64*68
    float* Ss   = Vs + BN * PAD;       // 64*68
    float* pmax = Ss + BM * PAD;       // 256
    float* psum = pmax + 256;          // 256
    float* mrow = psum + 256;          // 64
    float* lrow = mrow + 64;           // 64
    float* arow = lrow + 64;           // 64

    const int tid = threadIdx.x;
    const int lane = tid & 31, warp = tid >> 5;
    const int g = lane >> 2, tg = lane & 3;
    const int wm = (warp >> 2) * 32;   // 0 or 32
    const int wn = (warp & 3) * 16;    // 0,16,32,48
    const int q0 = blockIdx.x * BM;
    const int h = blockIdx.y;
    const int b = blockIdx.z;

    const float* Qb = Q + (size_t)(b * SEQ + q0) * DMODEL + h * DHEAD;
    const float* Kb = K + (size_t)(b * SEQ) * DMODEL + h * DHEAD;
    const float* Vb = V + (size_t)(b * SEQ) * DMODEL + h * DHEAD;

    // Load Q tile (tf32-converted)
#pragma unroll
    for (int t = 0; t < 4; t++) {
        int id = t * 256 + tid;
        int row = id >> 4;
        int d4 = (id & 15) * 4;
        float4 v = *(const float4*)(Qb + (size_t)row * DMODEL + d4);
        *(float4*)&Qs[row * PAD + d4] = cvt4(v);
    }
    if (tid < BM) { mrow[tid] = -INFINITY; lrow[tid] = 0.0f; }

    float oacc[2][2][4];
#pragma unroll
    for (int mt = 0; mt < 2; mt++)
#pragma unroll
        for (int nt = 0; nt < 2; nt++)
#pragma unroll
            for (int e = 0; e < 4; e++) oacc[mt][nt][e] = 0.0f;
    __syncthreads();

    for (int kv = 0; kv < SEQ; kv += BN) {
        // Load K & V tiles (tf32-converted)
#pragma unroll
        for (int t = 0; t < 4; t++) {
            int id = t * 256 + tid;
            int row = id >> 4;
            int d4 = (id & 15) * 4;
            float4 kk = *(const float4*)(Kb + (size_t)(kv + row) * DMODEL + d4);
            float4 vv = *(const float4*)(Vb + (size_t)(kv + row) * DMODEL + d4);
            *(float4*)&Ks[row * PAD + d4] = cvt4(kk);
            *(float4*)&Vs[row * PAD + d4] = cvt4(vv);
        }
        __syncthreads();

        // S = Q K^T
        float sacc[2][2][4];
#pragma unroll
        for (int mt = 0; mt < 2; mt++)
#pragma unroll
            for (int nt = 0; nt < 2; nt++)
#pragma unroll
                for (int e = 0; e < 4; e++) sacc[mt][nt][e] = 0.0f;

#pragma unroll
        for (int ks = 0; ks < DHEAD; ks += 8) {
            uint32_t af[2][4], bf[2][2];
#pragma unroll
            for (int mt = 0; mt < 2; mt++) {
                const float* p = &Qs[(wm + mt * 16 + g) * PAD + ks + tg];
                af[mt][0] = __float_as_uint(p[0]);
                af[mt][1] = __float_as_uint(p[8 * PAD]);
                af[mt][2] = __float_as_uint(p[4]);
                af[mt][3] = __float_as_uint(p[8 * PAD + 4]);
            }
#pragma unroll
            for (int nt = 0; nt < 2; nt++) {
                const float* p = &Ks[(wn + nt * 8 + g) * PAD + ks + tg];
                bf[nt][0] = __float_as_uint(p[0]);
                bf[nt][1] = __float_as_uint(p[4]);
            }
#pragma unroll
            for (int mt = 0; mt < 2; mt++)
#pragma unroll
                for (int nt = 0; nt < 2; nt++)
                    mma_tf32(sacc[mt][nt], af[mt], bf[nt]);
        }

        // Write scaled S to shared
#pragma unroll
        for (int mt = 0; mt < 2; mt++) {
            int r = wm + mt * 16 + g;
#pragma unroll
            for (int nt = 0; nt < 2; nt++) {
                int c = wn + nt * 8 + 2 * tg;
                *(float2*)&Ss[r * PAD + c]       = make_float2(sacc[mt][nt][0] * SCALE, sacc[mt][nt][1] * SCALE);
                *(float2*)&Ss[(r + 8) * PAD + c] = make_float2(sacc[mt][nt][2] * SCALE, sacc[mt][nt][3] * SCALE);
            }
        }
        __syncthreads();

        // partial row max: thread -> (row = tid>>2, 16-col segment)
        {
            int r = tid >> 2, c0 = (tid & 3) * 16;
            float mx = -INFINITY;
#pragma unroll
            for (int i = 0; i < 16; i++) mx = fmaxf(mx, Ss[r * PAD + c0 + i]);
            pmax[tid] = mx;
        }
        __syncthreads();
        if (tid < BM) {
            float mo = mrow[tid];
            float mx = fmaxf(fmaxf(pmax[tid * 4], pmax[tid * 4 + 1]),
                             fmaxf(pmax[tid * 4 + 2], pmax[tid * 4 + 3]));
            mx = fmaxf(mx, mo);
            arow[tid] = __expf(mo - mx);
            mrow[tid] = mx;
        }
        __syncthreads();

        // exp, partial sum, convert P to tf32 in place
        {
            int r = tid >> 2, c0 = (tid & 3) * 16;
            float m = mrow[r], s = 0.0f;
#pragma unroll
            for (int i = 0; i < 16; i++) {
                float p = __expf(Ss[r * PAD + c0 + i] - m);
                s += p;
                Ss[r * PAD + c0 + i] = __uint_as_float(f2tf32(p));
            }
            psum[tid] = s;
        }
        __syncthreads();
        if (tid < BM) {
            lrow[tid] = lrow[tid] * arow[tid]
                      + psum[tid * 4] + psum[tid * 4 + 1]
                      + psum[tid * 4 + 2] + psum[tid * 4 + 3];
        }

        // rescale O accumulators
#pragma unroll
        for (int mt = 0; mt < 2; mt++) {
            float a0 = arow[wm + mt * 16 + g];
            float a1 = arow[wm + mt * 16 + g + 8];
#pragma unroll
            for (int nt = 0; nt < 2; nt++) {
                oacc[mt][nt][0] *= a0; oacc[mt][nt][1] *= a0;
                oacc[mt][nt][2] *= a1; oacc[mt][nt][3] *= a1;
            }
        }

        // O += P @ V
#pragma unroll
        for (int ks = 0; ks < BN; ks += 8) {
            uint32_t af[2][4], bf[2][2];
#pragma unroll
            for (int mt = 0; mt < 2; mt++) {
                const float* p = &Ss[(wm + mt * 16 + g) * PAD + ks + tg];
                af[mt][0] = __float_as_uint(p[0]);
                af[mt][1] = __float_as_uint(p[8 * PAD]);
                af[mt][2] = __float_as_uint(p[4]);
                af[mt][3] = __float_as_uint(p[8 * PAD + 4]);
            }
#pragma unroll
            for (int nt = 0; nt < 2; nt++) {
                const float* p = &Vs[(ks + tg) * PAD + wn + nt * 8 + g];
                bf[nt][0] = __float_as_uint(p[0]);
                bf[nt][1] = __float_as_uint(p[4 * PAD]);
            }
#pragma unroll
            for (int mt = 0; mt < 2; mt++)
#pragma unroll
                for (int nt = 0; nt < 2; nt++)
                    mma_tf32(oacc[mt][nt], af[mt], bf[nt]);
        }
        __syncthreads();  // guard smem reuse next iteration (also publishes lrow)
    }

    // Epilogue: normalize and store
    float* Ob = O + (size_t)(b * SEQ + q0) * DMODEL + h * DHEAD;
#pragma unroll
    for (int mt = 0; mt < 2; mt++) {
        int r1 = wm + mt * 16 + g;
        int r2 = r1 + 8;
        float li1 = 1.0f / lrow[r1];
        float li2 = 1.0f / lrow[r2];
#pragma unroll
        for (int nt = 0; nt < 2; nt++) {
            int c = wn + nt * 8 + 2 * tg;
            *(float2*)(Ob + (size_t)r1 * DMODEL + c) = make_float2(oacc[mt][nt][0] * li1, oacc[mt][nt][1] * li1);
            *(float2*)(Ob + (size_t)r2 * DMODEL + c) = make_float2(oacc[mt][nt][2] * li2, oacc[mt][nt][3] * li2);
        }
    }
}

// ---------------------------------------------------------------------------

extern "C" void kernel_launch(void* const* d_in, const int* in_sizes, int n_in,
                              void* d_out, int out_size)
{
    const float* X  = (const float*)d_in[0];
    const float* Wq = (const float*)d_in[1];
    const float* Wk = (const float*)d_in[2];
    const float* Wv = (const float*)d_in[3];
    const float* Wo = (const float*)d_in[4];
    float* out = (float*)d_out;

    float *q, *k, *v, *ctx;
    cudaGetSymbolAddress((void**)&q,   g_q);
    cudaGetSymbolAddress((void**)&k,   g_k);
    cudaGetSymbolAddress((void**)&v,   g_v);
    cudaGetSymbolAddress((void**)&ctx, g_ctx);

    const int FLASH_SMEM = (4 * 64 * 68 + 256 + 256 + 3 * 64) * 4;  // 72448 B
    cudaFuncSetAttribute(flash_attn_tc, cudaFuncAttributeMaxDynamicSharedMemorySize, FLASH_SMEM);

    dim3 gproj(DMODEL / 128, MROWS / 128);   // (8, 64)
    gemm_nt_tc<<<gproj, 256>>>(X, Wq, q, MROWS, DMODEL, DMODEL);
    gemm_nt_tc<<<gproj, 256>>>(X, Wk, k, MROWS, DMODEL, DMODEL);
    gemm_nt_tc<<<gproj, 256>>>(X, Wv, v, MROWS, DMODEL, DMODEL);

    dim3 gattn(SEQ / 64, NHEAD, BATCH);      // (32, 16, 4)
    flash_attn_tc<<<gattn, 256, FLASH_SMEM>>>(q, k, v, ctx);

    gemm_nt_tc<<<gproj, 256>>>(ctx, Wo, out, MROWS, DMODEL, DMODEL);
}

// round 3
// speedup vs baseline: 6.0594x; 2.4005x over previous
#include <cuda_runtime.h>
#include <cuda_fp16.h>
#include <math.h>
#include <stdint.h>

#define BATCH 4
#define SEQ   2048
#define DMODEL 1024
#define NHEAD 16
#define DHEAD 64
#define MROWS (BATCH * SEQ)   // 8192

// Scratch (device globals: allocation-free, graph-capture safe)
__device__ float g_q[MROWS * DMODEL];
__device__ float g_k[MROWS * DMODEL];
__device__ float g_v[MROWS * DMODEL];
__device__ float g_ctx[MROWS * DMODEL];

// ---------------------------------------------------------------------------
// helpers
// ---------------------------------------------------------------------------
__device__ __forceinline__ uint32_t smem_u32(const void* p) {
    return (uint32_t)__cvta_generic_to_shared(p);
}
__device__ __forceinline__ void ldmx4(uint32_t& r0, uint32_t& r1, uint32_t& r2, uint32_t& r3,
                                      uint32_t addr) {
    asm volatile("ldmatrix.sync.aligned.m8n8.x4.shared.b16 {%0,%1,%2,%3}, [%4];"
                 : "=r"(r0), "=r"(r1), "=r"(r2), "=r"(r3) : "r"(addr));
}
__device__ __forceinline__ void ldmx4t(uint32_t& r0, uint32_t& r1, uint32_t& r2, uint32_t& r3,
                                       uint32_t addr) {
    asm volatile("ldmatrix.sync.aligned.m8n8.x4.trans.shared.b16 {%0,%1,%2,%3}, [%4];"
                 : "=r"(r0), "=r"(r1), "=r"(r2), "=r"(r3) : "r"(addr));
}
// D += A(16x16) * B(16x8), fp16 inputs, fp32 accum
__device__ __forceinline__ void mma16816(float d[4], uint32_t a0, uint32_t a1, uint32_t a2,
                                         uint32_t a3, uint32_t b0, uint32_t b1) {
    asm volatile(
        "mma.sync.aligned.m16n8k16.row.col.f32.f16.f16.f32 "
        "{%0,%1,%2,%3},{%4,%5,%6,%7},{%8,%9},{%0,%1,%2,%3};"
        : "+f"(d[0]), "+f"(d[1]), "+f"(d[2]), "+f"(d[3])
        : "r"(a0), "r"(a1), "r"(a2), "r"(a3), "r"(b0), "r"(b1));
}
__device__ __forceinline__ uint32_t pack_h2(float lo, float hi) {
    __half2 h = __floats2half2_rn(lo, hi);
    return *(uint32_t*)&h;
}

// ---------------------------------------------------------------------------
// C[m,n] = sum_k A[m,k] * W[n,k]  via fp16 m16n8k16 mma, fp32 accum.
// Block 128x128x32, 256 threads = 8 warps (2m x 4n), warp tile 64x32.
// ---------------------------------------------------------------------------
__global__ __launch_bounds__(256, 2) void gemm_nt_h(
    const float* __restrict__ A, const float* __restrict__ W,
    float* __restrict__ C, int M, int N, int K)
{
    constexpr int PAD = 40;   // halfs per row (32 + 8): 80B stride, ldmatrix conflict-free
    __shared__ __half As[128 * PAD];
    __shared__ __half Bs[128 * PAD];

    const int tid = threadIdx.x;
    const int lane = tid & 31, warp = tid >> 5;
    const int m0 = blockIdx.y * 128, n0 = blockIdx.x * 128;
    const int wm = (warp >> 2) * 64;
    const int wn = (warp & 3) * 32;

    // ldmatrix per-lane address components
    const int rowA = (lane & 7) + 8 * ((lane >> 3) & 1);  // + 8*(lane>>4) col
    const int colA = 8 * (lane >> 4);
    const int rowB = (lane & 7) + 8 * (lane >> 4);
    const int colB = 8 * ((lane >> 3) & 1);

    uint32_t aAddr[4], bAddr[2];
#pragma unroll
    for (int mt = 0; mt < 4; mt++)
        aAddr[mt] = smem_u32(&As[(wm + mt * 16 + rowA) * PAD + colA]);
#pragma unroll
    for (int p = 0; p < 2; p++)
        bAddr[p] = smem_u32(&Bs[(wn + p * 16 + rowB) * PAD + colB]);

    const int ldrow = tid >> 3;         // 0..31
    const int ldk   = (tid & 7) * 4;    // 0,4,..28

    float acc[4][4][4];
#pragma unroll
    for (int mt = 0; mt < 4; mt++)
#pragma unroll
        for (int nt = 0; nt < 4; nt++)
#pragma unroll
            for (int e = 0; e < 4; e++) acc[mt][nt][e] = 0.0f;

    float4 ra[4], rb[4];
#pragma unroll
    for (int t = 0; t < 4; t++) {
        int row = ldrow + t * 32;
        ra[t] = *(const float4*)(A + (size_t)(m0 + row) * K + ldk);
        rb[t] = *(const float4*)(W + (size_t)(n0 + row) * K + ldk);
    }

    const int NITER = K / 32;
    for (int it = 0; it < NITER; it++) {
        // stage regs -> smem (fp16)
#pragma unroll
        for (int t = 0; t < 4; t++) {
            int row = ldrow + t * 32;
            __half2* pa = (__half2*)&As[row * PAD + ldk];
            pa[0] = __floats2half2_rn(ra[t].x, ra[t].y);
            pa[1] = __floats2half2_rn(ra[t].z, ra[t].w);
            __half2* pb = (__half2*)&Bs[row * PAD + ldk];
            pb[0] = __floats2half2_rn(rb[t].x, rb[t].y);
            pb[1] = __floats2half2_rn(rb[t].z, rb[t].w);
        }
        __syncthreads();

        if (it + 1 < NITER) {
            int k0 = (it + 1) * 32;
#pragma unroll
            for (int t = 0; t < 4; t++) {
                int row = ldrow + t * 32;
                ra[t] = *(const float4*)(A + (size_t)(m0 + row) * K + k0 + ldk);
                rb[t] = *(const float4*)(W + (size_t)(n0 + row) * K + k0 + ldk);
            }
        }

#pragma unroll
        for (int ks = 0; ks < 32; ks += 16) {
            uint32_t af[4][4], bf[4][2];
#pragma unroll
            for (int mt = 0; mt < 4; mt++)
                ldmx4(af[mt][0], af[mt][1], af[mt][2], af[mt][3], aAddr[mt] + ks * 2);
#pragma unroll
            for (int p = 0; p < 2; p++)
                ldmx4(bf[2 * p][0], bf[2 * p][1], bf[2 * p + 1][0], bf[2 * p + 1][1],
                      bAddr[p] + ks * 2);
#pragma unroll
            for (int mt = 0; mt < 4; mt++)
#pragma unroll
                for (int nt = 0; nt < 4; nt++)
                    mma16816(acc[mt][nt], af[mt][0], af[mt][1], af[mt][2], af[mt][3],
                             bf[nt][0], bf[nt][1]);
        }
        __syncthreads();
    }

    const int g = lane >> 2, tg = lane & 3;
#pragma unroll
    for (int mt = 0; mt < 4; mt++) {
        int r0 = m0 + wm + mt * 16 + g;
#pragma unroll
        for (int nt = 0; nt < 4; nt++) {
            int c = n0 + wn + nt * 8 + 2 * tg;
            *(float2*)(C + (size_t)r0 * N + c)       = make_float2(acc[mt][nt][0], acc[mt][nt][1]);
            *(float2*)(C + (size_t)(r0 + 8) * N + c) = make_float2(acc[mt][nt][2], acc[mt][nt][3]);
        }
    }
}

// ---------------------------------------------------------------------------
// Flash attention, fp16 mma, register softmax (FA2 layout).
// grid=(SEQ/128, H, B), 256 threads = 8 warps, each warp: 16 q-rows.
// BM=128, BN=64, DHEAD=64. S never hits smem.
// ---------------------------------------------------------------------------
__global__ __launch_bounds__(256, 2) void flash_attn_h(
    const float* __restrict__ Q, const float* __restrict__ K,
    const float* __restrict__ V, float* __restrict__ O)
{
    constexpr int BM = 128, BN = 64, PAD = 72;  // half stride: 144B, ldmatrix conflict-free
    constexpr float SCALE = 0.125f;             // 1/sqrt(64), exact in fp16

    __shared__ __half Qs[BM * PAD];
    __shared__ __half Ks[BN * PAD];
    __shared__ __half Vs[BN * PAD];

    const int tid = threadIdx.x;
    const int lane = tid & 31, warp = tid >> 5;
    const int g = lane >> 2, tg = lane & 3;
    const int wm = warp * 16;
    const int q0 = blockIdx.x * BM;
    const int h = blockIdx.y;
    const int b = blockIdx.z;

    const float* Qb = Q + (size_t)(b * SEQ + q0) * DMODEL + h * DHEAD;
    const float* Kb = K + (size_t)(b * SEQ) * DMODEL + h * DHEAD;
    const float* Vb = V + (size_t)(b * SEQ) * DMODEL + h * DHEAD;

    const int ldrow = tid >> 4;        // 0..15
    const int ldd   = (tid & 15) * 4;  // 0..60

    // Load Q tile (scaled, fp16): 128 rows x 64 cols
#pragma unroll
    for (int t = 0; t < 8; t++) {
        int row = ldrow + t * 16;
        float4 v = *(const float4*)(Qb + (size_t)row * DMODEL + ldd);
        __half2* p = (__half2*)&Qs[row * PAD + ldd];
        p[0] = __floats2half2_rn(v.x * SCALE, v.y * SCALE);
        p[1] = __floats2half2_rn(v.z * SCALE, v.w * SCALE);
    }
    __syncthreads();

    // Preload Q fragments for this warp's 16 rows (4 k-steps)
    const int rowA = (lane & 7) + 8 * ((lane >> 3) & 1);
    const int colA = 8 * (lane >> 4);
    const int rowB = (lane & 7) + 8 * (lane >> 4);
    const int colB = 8 * ((lane >> 3) & 1);

    uint32_t qf[4][4];
#pragma unroll
    for (int j = 0; j < 4; j++)
        ldmx4(qf[j][0], qf[j][1], qf[j][2], qf[j][3],
              smem_u32(&Qs[(wm + rowA) * PAD + 16 * j + colA]));

    uint32_t kAddr[4], vAddr[4];
#pragma unroll
    for (int p = 0; p < 4; p++) {
        kAddr[p] = smem_u32(&Ks[(p * 16 + rowB) * PAD + colB]);       // + 32*j bytes
        vAddr[p] = smem_u32(&Vs[rowA * PAD + p * 16 + colA]);         // + 2304*j bytes
    }

    float oacc[8][4];
#pragma unroll
    for (int nt = 0; nt < 8; nt++)
#pragma unroll
        for (int e = 0; e < 4; e++) oacc[nt][e] = 0.0f;
    float m0r = -INFINITY, m1r = -INFINITY, l0r = 0.0f, l1r = 0.0f;

    for (int kv = 0; kv < SEQ; kv += BN) {
        __syncthreads();
        // Load K,V tiles (fp16): 64 x 64 each
#pragma unroll
        for (int t = 0; t < 4; t++) {
            int row = ldrow + t * 16;
            float4 kk = *(const float4*)(Kb + (size_t)(kv + row) * DMODEL + ldd);
            float4 vv = *(const float4*)(Vb + (size_t)(kv + row) * DMODEL + ldd);
            __half2* pk = (__half2*)&Ks[row * PAD + ldd];
            pk[0] = __floats2half2_rn(kk.x, kk.y);
            pk[1] = __floats2half2_rn(kk.z, kk.w);
            __half2* pv = (__half2*)&Vs[row * PAD + ldd];
            pv[0] = __floats2half2_rn(vv.x, vv.y);
            pv[1] = __floats2half2_rn(vv.z, vv.w);
        }
        __syncthreads();

        // S = (Q*scale) K^T : warp computes 16 x 64
        float sacc[8][4];
#pragma unroll
        for (int nt = 0; nt < 8; nt++)
#pragma unroll
            for (int e = 0; e < 4; e++) sacc[nt][e] = 0.0f;

#pragma unroll
        for (int j = 0; j < 4; j++) {       // k-steps over DHEAD
#pragma unroll
            for (int p = 0; p < 4; p++) {   // n-tile pairs over BN
                uint32_t b0, b1, b2, b3;
                ldmx4(b0, b1, b2, b3, kAddr[p] + 32 * j);
                mma16816(sacc[2 * p],     qf[j][0], qf[j][1], qf[j][2], qf[j][3], b0, b1);
                mma16816(sacc[2 * p + 1], qf[j][0], qf[j][1], qf[j][2], qf[j][3], b2, b3);
            }
        }

        // Register softmax: rows g (e0,e1) and g+8 (e2,e3)
        float mx0 = -INFINITY, mx1 = -INFINITY;
#pragma unroll
        for (int nt = 0; nt < 8; nt++) {
            mx0 = fmaxf(mx0, fmaxf(sacc[nt][0], sacc[nt][1]));
            mx1 = fmaxf(mx1, fmaxf(sacc[nt][2], sacc[nt][3]));
        }
        mx0 = fmaxf(mx0, __shfl_xor_sync(0xffffffffu, mx0, 1));
        mx0 = fmaxf(mx0, __shfl_xor_sync(0xffffffffu, mx0, 2));
        mx1 = fmaxf(mx1, __shfl_xor_sync(0xffffffffu, mx1, 1));
        mx1 = fmaxf(mx1, __shfl_xor_sync(0xffffffffu, mx1, 2));

        float mn0 = fmaxf(m0r, mx0), mn1 = fmaxf(m1r, mx1);
        float a0 = __expf(m0r - mn0), a1 = __expf(m1r - mn1);
        m0r = mn0; m1r = mn1;

        float s0 = 0.0f, s1 = 0.0f;
        uint32_t ph[8][2];
#pragma unroll
        for (int nt = 0; nt < 8; nt++) {
            float p0 = __expf(sacc[nt][0] - mn0);
            float p1 = __expf(sacc[nt][1] - mn0);
            float p2 = __expf(sacc[nt][2] - mn1);
            float p3 = __expf(sacc[nt][3] - mn1);
            s0 += p0 + p1; s1 += p2 + p3;
            ph[nt][0] = pack_h2(p0, p1);
            ph[nt][1] = pack_h2(p2, p3);
        }
        s0 += __shfl_xor_sync(0xffffffffu, s0, 1);
        s0 += __shfl_xor_sync(0xffffffffu, s0, 2);
        s1 += __shfl_xor_sync(0xffffffffu, s1, 1);
        s1 += __shfl_xor_sync(0xffffffffu, s1, 2);
        l0r = l0r * a0 + s0;
        l1r = l1r * a1 + s1;

#pragma unroll
        for (int nt = 0; nt < 8; nt++) {
            oacc[nt][0] *= a0; oacc[nt][1] *= a0;
            oacc[nt][2] *= a1; oacc[nt][3] *= a1;
        }

        // O += P @ V : P fragments are the softmax registers (FA2 layout reuse)
#pragma unroll
        for (int j = 0; j < 4; j++) {       // k-steps over BN
#pragma unroll
            for (int p = 0; p < 4; p++) {   // n-tile pairs over DHEAD
                uint32_t v0, v1, v2, v3;
                ldmx4t(v0, v1, v2, v3, vAddr[p] + 2304 * j);
                mma16816(oacc[2 * p],     ph[2 * j][0], ph[2 * j][1],
                         ph[2 * j + 1][0], ph[2 * j + 1][1], v0, v1);
                mma16816(oacc[2 * p + 1], ph[2 * j][0], ph[2 * j][1],
                         ph[2 * j + 1][0], ph[2 * j + 1][1], v2, v3);
            }
        }
    }

    // Epilogue
    float inv0 = 1.0f / l0r, inv1 = 1.0f / l1r;
    float* Ob = O + (size_t)(b * SEQ + q0 + wm) * DMODEL + h * DHEAD;
#pragma unroll
    for (int nt = 0; nt < 8; nt++) {
        int c = nt * 8 + 2 * tg;
        *(float2*)(Ob + (size_t)g * DMODEL + c)       = make_float2(oacc[nt][0] * inv0, oacc[nt][1] * inv0);
        *(float2*)(Ob + (size_t)(g + 8) * DMODEL + c) = make_float2(oacc[nt][2] * inv1, oacc[nt][3] * inv1);
    }
}

// ---------------------------------------------------------------------------

extern "C" void kernel_launch(void* const* d_in, const int* in_sizes, int n_in,
                              void* d_out, int out_size)
{
    const float* X  = (const float*)d_in[0];
    const float* Wq = (const float*)d_in[1];
    const float* Wk = (const float*)d_in[2];
    const float* Wv = (const float*)d_in[3];
    const float* Wo = (const float*)d_in[4];
    float* out = (float*)d_out;

    float *q, *k, *v, *ctx;
    cudaGetSymbolAddress((void**)&q,   g_q);
    cudaGetSymbolAddress((void**)&k,   g_k);
    cudaGetSymbolAddress((void**)&v,   g_v);
    cudaGetSymbolAddress((void**)&ctx, g_ctx);

    dim3 gproj(DMODEL / 128, MROWS / 128);   // (8, 64)
    gemm_nt_h<<<gproj, 256>>>(X, Wq, q, MROWS, DMODEL, DMODEL);
    gemm_nt_h<<<gproj, 256>>>(X, Wk, k, MROWS, DMODEL, DMODEL);
    gemm_nt_h<<<gproj, 256>>>(X, Wv, v, MROWS, DMODEL, DMODEL);

    dim3 gattn(SEQ / 128, NHEAD, BATCH);     // (16, 16, 4)
    flash_attn_h<<<gattn, 256>>>(q, k, v, ctx);

    gemm_nt_h<<<gproj, 256>>>(ctx, Wo, out, MROWS, DMODEL, DMODEL);
}

// round 5
// speedup vs baseline: 6.7303x; 1.1107x over previous
#include <cuda_runtime.h>
#include <cuda_fp16.h>
#include <math.h>
#include <stdint.h>

#define BATCH 4
#define SEQ   2048
#define DMODEL 1024
#define NHEAD 16
#define DHEAD 64
#define MROWS (BATCH * SEQ)   // 8192

// Scratch (device globals: allocation-free, graph-capture safe)
__device__ __half g_xh[MROWS * DMODEL];
__device__ __half g_wq[DMODEL * DMODEL];
__device__ __half g_wk[DMODEL * DMODEL];
__device__ __half g_wv[DMODEL * DMODEL];
__device__ __half g_wo[DMODEL * DMODEL];
__device__ __half g_q[MROWS * DMODEL];
__device__ __half g_k[MROWS * DMODEL];
__device__ __half g_v[MROWS * DMODEL];
__device__ __half g_ctx[MROWS * DMODEL];

// ---------------------------------------------------------------------------
// helpers
// ---------------------------------------------------------------------------
__device__ __forceinline__ uint32_t smem_u32(const void* p) {
    return (uint32_t)__cvta_generic_to_shared(p);
}
__device__ __forceinline__ void cp16(uint32_t s, const void* g) {
    asm volatile("cp.async.cg.shared.global [%0], [%1], 16;" :: "r"(s), "l"(g));
}
__device__ __forceinline__ void cp_commit() {
    asm volatile("cp.async.commit_group;");
}
template <int N>
__device__ __forceinline__ void cp_wait() {
    asm volatile("cp.async.wait_group %0;" :: "n"(N));
}
__device__ __forceinline__ void ldmx4(uint32_t& r0, uint32_t& r1, uint32_t& r2, uint32_t& r3,
                                      uint32_t addr) {
    asm volatile("ldmatrix.sync.aligned.m8n8.x4.shared.b16 {%0,%1,%2,%3}, [%4];"
                 : "=r"(r0), "=r"(r1), "=r"(r2), "=r"(r3) : "r"(addr));
}
__device__ __forceinline__ void ldmx4t(uint32_t& r0, uint32_t& r1, uint32_t& r2, uint32_t& r3,
                                       uint32_t addr) {
    asm volatile("ldmatrix.sync.aligned.m8n8.x4.trans.shared.b16 {%0,%1,%2,%3}, [%4];"
                 : "=r"(r0), "=r"(r1), "=r"(r2), "=r"(r3) : "r"(addr));
}
__device__ __forceinline__ void mma16816(float d[4], uint32_t a0, uint32_t a1, uint32_t a2,
                                         uint32_t a3, uint32_t b0, uint32_t b1) {
    asm volatile(
        "mma.sync.aligned.m16n8k16.row.col.f32.f16.f16.f32 "
        "{%0,%1,%2,%3},{%4,%5,%6,%7},{%8,%9},{%0,%1,%2,%3};"
        : "+f"(d[0]), "+f"(d[1]), "+f"(d[2]), "+f"(d[3])
        : "r"(a0), "r"(a1), "r"(a2), "r"(a3), "r"(b0), "r"(b1));
}
__device__ __forceinline__ uint32_t pack_h2(float lo, float hi) {
    __half2 h = __floats2half2_rn(lo, hi);
    return *(uint32_t*)&h;
}

// ---------------------------------------------------------------------------
// fp32 -> fp16 conversion (one-shot, bandwidth-bound). n % 8 == 0.
// ---------------------------------------------------------------------------
__global__ __launch_bounds__(256) void cvt_f2h(const float* __restrict__ in,
                                               __half* __restrict__ out, int n) {
    for (int i = (blockIdx.x * blockDim.x + threadIdx.x) * 8; i < n;
         i += gridDim.x * blockDim.x * 8) {
        float4 a = *(const float4*)(in + i);
        float4 b = *(const float4*)(in + i + 4);
        __half2 h[4];
        h[0] = __floats2half2_rn(a.x, a.y);
        h[1] = __floats2half2_rn(a.z, a.w);
        h[2] = __floats2half2_rn(b.x, b.y);
        h[3] = __floats2half2_rn(b.z, b.w);
        *(uint4*)(out + i) = *(uint4*)h;
    }
}

// ---------------------------------------------------------------------------
// C[m,n] = scale * sum_k A[m,k] * W[n,k]  (fp16 in, OutT out)
// 128x128x32 tile, 256 thr = 8 warps (2m x 4n), warp 64x32, 3-stage cp.async.
// ---------------------------------------------------------------------------
template <typename OutT>
__global__ __launch_bounds__(256) void gemm_h16(
    const __half* __restrict__ A, const __half* __restrict__ W,
    OutT* __restrict__ C, int M, int N, int K, float scale)
{
    constexpr int PAD = 40;      // halves/row: 80B stride (16B aligned, LDSM conflict-free)
    constexpr int BK = 32, STAGES = 3;
    constexpr int TILE = 128 * PAD;          // halves per stage per matrix
    extern __shared__ __half dynsm[];
    __half* As = dynsm;                      // STAGES*TILE
    __half* Bs = dynsm + STAGES * TILE;

    const int tid = threadIdx.x;
    const int lane = tid & 31, warp = tid >> 5;
    const int m0 = blockIdx.y * 128, n0 = blockIdx.x * 128;
    const int wm = (warp >> 2) * 64;
    const int wn = (warp & 3) * 32;

    const uint32_t sA = smem_u32(As);
    const uint32_t sB = smem_u32(Bs);

    // cp.async mapping: 512 chunks (128 rows x 4 x 16B) per matrix, 2 per thread
    const int ldrow = tid >> 2;
    const int ldko  = (tid & 3) * 8;

    auto issue = [&](int kb, int s) {
#pragma unroll
        for (int t = 0; t < 2; t++) {
            int row = ldrow + t * 64;
            uint32_t off = (uint32_t)((s * 128 + row) * PAD + ldko) * 2;
            cp16(sA + off, A + (size_t)(m0 + row) * K + kb * BK + ldko);
            cp16(sB + off, W + (size_t)(n0 + row) * K + kb * BK + ldko);
        }
        cp_commit();
    };

    // ldmatrix lane addressing
    const int rowA = (lane & 7) + 8 * ((lane >> 3) & 1);
    const int colA = 8 * (lane >> 4);
    const int rowB = (lane & 7) + 8 * (lane >> 4);
    const int colB = 8 * ((lane >> 3) & 1);

    uint32_t aAddr[4], bAddr[2];
#pragma unroll
    for (int mt = 0; mt < 4; mt++)
        aAddr[mt] = smem_u32(&As[(wm + mt * 16 + rowA) * PAD + colA]);
#pragma unroll
    for (int p = 0; p < 2; p++)
        bAddr[p] = smem_u32(&Bs[(wn + p * 16 + rowB) * PAD + colB]);

    float acc[4][4][4];
#pragma unroll
    for (int mt = 0; mt < 4; mt++)
#pragma unroll
        for (int nt = 0; nt < 4; nt++)
#pragma unroll
            for (int e = 0; e < 4; e++) acc[mt][nt][e] = 0.0f;

    const int NITER = K / BK;   // 32
#pragma unroll
    for (int s = 0; s < STAGES; s++) issue(s, s);

    for (int it = 0; it < NITER; it++) {
        if (it < NITER - 2)       cp_wait<2>();
        else if (it == NITER - 2) cp_wait<1>();
        else                      cp_wait<0>();
        __syncthreads();

        const int s = it % STAGES;
        const uint32_t soff = (uint32_t)(s * TILE) * 2;

#pragma unroll
        for (int ks = 0; ks < BK; ks += 16) {
            uint32_t af[4][4], bf[4][2];
#pragma unroll
            for (int mt = 0; mt < 4; mt++)
                ldmx4(af[mt][0], af[mt][1], af[mt][2], af[mt][3],
                      aAddr[mt] + soff + ks * 2);
#pragma unroll
            for (int p = 0; p < 2; p++)
                ldmx4(bf[2 * p][0], bf[2 * p][1], bf[2 * p + 1][0], bf[2 * p + 1][1],
                      bAddr[p] + soff + ks * 2);
#pragma unroll
            for (int mt = 0; mt < 4; mt++)
#pragma unroll
                for (int nt = 0; nt < 4; nt++)
                    mma16816(acc[mt][nt], af[mt][0], af[mt][1], af[mt][2], af[mt][3],
                             bf[nt][0], bf[nt][1]);
        }
        __syncthreads();
        if (it + STAGES < NITER) issue(it + STAGES, s);
    }

    const int g = lane >> 2, tg = lane & 3;
#pragma unroll
    for (int mt = 0; mt < 4; mt++) {
        int r0 = m0 + wm + mt * 16 + g;
#pragma unroll
        for (int nt = 0; nt < 4; nt++) {
            int c = n0 + wn + nt * 8 + 2 * tg;
            if constexpr (sizeof(OutT) == 2) {
                *(__half2*)((__half*)C + (size_t)r0 * N + c) =
                    __floats2half2_rn(acc[mt][nt][0] * scale, acc[mt][nt][1] * scale);
                *(__half2*)((__half*)C + (size_t)(r0 + 8) * N + c) =
                    __floats2half2_rn(acc[mt][nt][2] * scale, acc[mt][nt][3] * scale);
            } else {
                *(float2*)((float*)C + (size_t)r0 * N + c) =
                    make_float2(acc[mt][nt][0] * scale, acc[mt][nt][1] * scale);
                *(float2*)((float*)C + (size_t)(r0 + 8) * N + c) =
                    make_float2(acc[mt][nt][2] * scale, acc[mt][nt][3] * scale);
            }
        }
    }
}

// ---------------------------------------------------------------------------
// Flash attention, fp16 in/out, register softmax, double-buffered cp.async K/V.
// grid=(SEQ/128, H, B), 256 thr = 8 warps, warp = 16 q-rows. Q pre-scaled.
// ---------------------------------------------------------------------------
__global__ __launch_bounds__(256) void flash_attn_h(
    const __half* __restrict__ Q, const __half* __restrict__ K,
    const __half* __restrict__ V, __half* __restrict__ O)
{
    constexpr int BM = 128, BN = 64, PAD = 72;   // 144B row stride
    constexpr int KVT = 64 * PAD;                // halves per K or V stage
    extern __shared__ __half fsm[];
    __half* Qs = fsm;                 // 128*PAD
    __half* Ks = Qs + 128 * PAD;      // 2 stages
    __half* Vs = Ks + 2 * KVT;        // 2 stages

    const int tid = threadIdx.x;
    const int lane = tid & 31, warp = tid >> 5;
    const int g = lane >> 2, tg = lane & 3;
    const int wm = warp * 16;
    const int q0 = blockIdx.x * BM;
    const int h = blockIdx.y;
    const int b = blockIdx.z;

    const __half* Qb = Q + (size_t)(b * SEQ + q0) * DMODEL + h * DHEAD;
    const __half* Kb = K + (size_t)(b * SEQ) * DMODEL + h * DHEAD;
    const __half* Vb = V + (size_t)(b * SEQ) * DMODEL + h * DHEAD;

    const uint32_t sK = smem_u32(Ks);
    const uint32_t sV = smem_u32(Vs);

    // K/V cp.async mapping: 512 chunks each (64 rows x 8 x 16B), 2 per thread
    const int ldrow = tid >> 3;       // 0..31
    const int ldoff = (tid & 7) * 8;  // halves

    auto issue_kv = [&](int t, int s) {
#pragma unroll
        for (int tt = 0; tt < 2; tt++) {
            int row = ldrow + tt * 32;
            uint32_t off = (uint32_t)(s * KVT + row * PAD + ldoff) * 2;
            const size_t gofs = (size_t)(t * BN + row) * DMODEL + ldoff;
            cp16(sK + off, Kb + gofs);
            cp16(sV + off, Vb + gofs);
        }
        cp_commit();
    };

    // Load Q tile (plain, once): 1024 chunks of 8 halves
#pragma unroll
    for (int t = 0; t < 4; t++) {
        int c = tid + t * 256;
        int row = c >> 3;
        int off = (c & 7) * 8;
        *(uint4*)&Qs[row * PAD + off] = *(const uint4*)(Qb + (size_t)row * DMODEL + off);
    }
    issue_kv(0, 0);
    __syncthreads();

    // ldmatrix lane addressing
    const int rowA = (lane & 7) + 8 * ((lane >> 3) & 1);
    const int colA = 8 * (lane >> 4);
    const int rowB = (lane & 7) + 8 * (lane >> 4);
    const int colB = 8 * ((lane >> 3) & 1);

    uint32_t qf[4][4];
#pragma unroll
    for (int j = 0; j < 4; j++)
        ldmx4(qf[j][0], qf[j][1], qf[j][2], qf[j][3],
              smem_u32(&Qs[(wm + rowA) * PAD + 16 * j + colA]));

    uint32_t kAddr[4], vAddr[4];
#pragma unroll
    for (int p = 0; p < 4; p++) {
        kAddr[p] = smem_u32(&Ks[(p * 16 + rowB) * PAD + colB]);   // +32*j, +stage*2*KVT
        vAddr[p] = smem_u32(&Vs[rowA * PAD + p * 16 + colA]);     // +2304*j, +stage*2*KVT
    }

    float oacc[8][4];
#pragma unroll
    for (int nt = 0; nt < 8; nt++)
#pragma unroll
        for (int e = 0; e < 4; e++) oacc[nt][e] = 0.0f;
    float m0r = -INFINITY, m1r = -INFINITY, l0r = 0.0f, l1r = 0.0f;

    const int NT = SEQ / BN;   // 32
    for (int t = 0; t < NT; t++) {
        if (t + 1 < NT) { issue_kv(t + 1, (t + 1) & 1); cp_wait<1>(); }
        else            { cp_wait<0>(); }
        __syncthreads();

        const uint32_t soff = (uint32_t)((t & 1) * KVT) * 2;

        // S = Q K^T (warp: 16 x 64)
        float sacc[8][4];
#pragma unroll
        for (int nt = 0; nt < 8; nt++)
#pragma unroll
            for (int e = 0; e < 4; e++) sacc[nt][e] = 0.0f;

#pragma unroll
        for (int j = 0; j < 4; j++) {
#pragma unroll
            for (int p = 0; p < 4; p++) {
                uint32_t b0, b1, b2, b3;
                ldmx4(b0, b1, b2, b3, kAddr[p] + soff + 32 * j);
                mma16816(sacc[2 * p],     qf[j][0], qf[j][1], qf[j][2], qf[j][3], b0, b1);
                mma16816(sacc[2 * p + 1], qf[j][0], qf[j][1], qf[j][2], qf[j][3], b2, b3);
            }
        }

        // Register softmax (rows g and g+8)
        float mx0 = -INFINITY, mx1 = -INFINITY;
#pragma unroll
        for (int nt = 0; nt < 8; nt++) {
            mx0 = fmaxf(mx0, fmaxf(sacc[nt][0], sacc[nt][1]));
            mx1 = fmaxf(mx1, fmaxf(sacc[nt][2], sacc[nt][3]));
        }
        mx0 = fmaxf(mx0, __shfl_xor_sync(0xffffffffu, mx0, 1));
        mx0 = fmaxf(mx0, __shfl_xor_sync(0xffffffffu, mx0, 2));
        mx1 = fmaxf(mx1, __shfl_xor_sync(0xffffffffu, mx1, 1));
        mx1 = fmaxf(mx1, __shfl_xor_sync(0xffffffffu, mx1, 2));

        float mn0 = fmaxf(m0r, mx0), mn1 = fmaxf(m1r, mx1);
        float a0 = __expf(m0r - mn0), a1 = __expf(m1r - mn1);
        m0r = mn0; m1r = mn1;

        float s0 = 0.0f, s1 = 0.0f;
        uint32_t ph[8][2];
#pragma unroll
        for (int nt = 0; nt < 8; nt++) {
            float p0 = __expf(sacc[nt][0] - mn0);
            float p1 = __expf(sacc[nt][1] - mn0);
            float p2 = __expf(sacc[nt][2] - mn1);
            float p3 = __expf(sacc[nt][3] - mn1);
            s0 += p0 + p1; s1 += p2 + p3;
            ph[nt][0] = pack_h2(p0, p1);
            ph[nt][1] = pack_h2(p2, p3);
        }
        s0 += __shfl_xor_sync(0xffffffffu, s0, 1);
        s0 += __shfl_xor_sync(0xffffffffu, s0, 2);
        s1 += __shfl_xor_sync(0xffffffffu, s1, 1);
        s1 += __shfl_xor_sync(0xffffffffu, s1, 2);
        l0r = l0r * a0 + s0;
        l1r = l1r * a1 + s1;

#pragma unroll
        for (int nt = 0; nt < 8; nt++) {
            oacc[nt][0] *= a0; oacc[nt][1] *= a0;
            oacc[nt][2] *= a1; oacc[nt][3] *= a1;
        }

        // O += P @ V
#pragma unroll
        for (int j = 0; j < 4; j++) {
#pragma unroll
            for (int p = 0; p < 4; p++) {
                uint32_t v0, v1, v2, v3;
                ldmx4t(v0, v1, v2, v3, vAddr[p] + soff + 2304 * j);
                mma16816(oacc[2 * p],     ph[2 * j][0], ph[2 * j][1],
                         ph[2 * j + 1][0], ph[2 * j + 1][1], v0, v1);
                mma16816(oacc[2 * p + 1], ph[2 * j][0], ph[2 * j][1],
                         ph[2 * j + 1][0], ph[2 * j + 1][1], v2, v3);
            }
        }
        __syncthreads();   // guard double-buffer overwrite by next iter's issue_kv
    }

    // Epilogue: normalize, write ctx fp16
    float inv0 = 1.0f / l0r, inv1 = 1.0f / l1r;
    __half* Ob = O + (size_t)(b * SEQ + q0 + wm) * DMODEL + h * DHEAD;
#pragma unroll
    for (int nt = 0; nt < 8; nt++) {
        int c = nt * 8 + 2 * tg;
        *(__half2*)(Ob + (size_t)g * DMODEL + c) =
            __floats2half2_rn(oacc[nt][0] * inv0, oacc[nt][1] * inv0);
        *(__half2*)(Ob + (size_t)(g + 8) * DMODEL + c) =
            __floats2half2_rn(oacc[nt][2] * inv1, oacc[nt][3] * inv1);
    }
}

// ---------------------------------------------------------------------------

extern "C" void kernel_launch(void* const* d_in, const int* in_sizes, int n_in,
                              void* d_out, int out_size)
{
    const float* X  = (const float*)d_in[0];
    const float* Wq = (const float*)d_in[1];
    const float* Wk = (const float*)d_in[2];
    const float* Wv = (const float*)d_in[3];
    const float* Wo = (const float*)d_in[4];
    float* out = (float*)d_out;

    __half *xh, *wq, *wk, *wv, *wo, *q, *k, *v, *ctx;
    cudaGetSymbolAddress((void**)&xh, g_xh);
    cudaGetSymbolAddress((void**)&wq, g_wq);
    cudaGetSymbolAddress((void**)&wk, g_wk);
    cudaGetSymbolAddress((void**)&wv, g_wv);
    cudaGetSymbolAddress((void**)&wo, g_wo);
    cudaGetSymbolAddress((void**)&q,  g_q);
    cudaGetSymbolAddress((void**)&k,  g_k);
    cudaGetSymbolAddress((void**)&v,  g_v);
    cudaGetSymbolAddress((void**)&ctx, g_ctx);

    const int GEMM_SMEM  = 3 * 2 * 128 * 40 * 2;               // 61440 B
    const int FLASH_SMEM = (128 * 72 + 4 * 64 * 72) * 2;       // 55296 B
    cudaFuncSetAttribute(gemm_h16<__half>, cudaFuncAttributeMaxDynamicSharedMemorySize, GEMM_SMEM);
    cudaFuncSetAttribute(gemm_h16<float>,  cudaFuncAttributeMaxDynamicSharedMemorySize, GEMM_SMEM);
    cudaFuncSetAttribute(flash_attn_h,     cudaFuncAttributeMaxDynamicSharedMemorySize, FLASH_SMEM);

    const int NX = MROWS * DMODEL;      // 8.4M
    const int NW = DMODEL * DMODEL;     // 1.05M
    cvt_f2h<<<NX / 2048, 256>>>(X,  xh, NX);
    cvt_f2h<<<NW / 2048, 256>>>(Wq, wq, NW);
    cvt_f2h<<<NW / 2048, 256>>>(Wk, wk, NW);
    cvt_f2h<<<NW / 2048, 256>>>(Wv, wv, NW);
    cvt_f2h<<<NW / 2048, 256>>>(Wo, wo, NW);

    dim3 gproj(DMODEL / 128, MROWS / 128);   // (8, 64)
    gemm_h16<__half><<<gproj, 256, GEMM_SMEM>>>(xh, wq, q, MROWS, DMODEL, DMODEL, 0.125f);
    gemm_h16<__half><<<gproj, 256, GEMM_SMEM>>>(xh, wk, k, MROWS, DMODEL, DMODEL, 1.0f);
    gemm_h16<__half><<<gproj, 256, GEMM_SMEM>>>(xh, wv, v, MROWS, DMODEL, DMODEL, 1.0f);

    dim3 gattn(SEQ / 128, NHEAD, BATCH);     // (16, 16, 4)
    flash_attn_h<<<gattn, 256, FLASH_SMEM>>>(q, k, v, ctx);

    gemm_h16<float><<<gproj, 256, GEMM_SMEM>>>(ctx, wo, out, MROWS, DMODEL, DMODEL, 1.0f);
}